// round 13
// baseline (speedup 1.0000x reference)
#include <cuda_runtime.h>
#include <math.h>

#define BB 4
#define HH 544
#define WW 960
#define H2 272
#define W2 480
#define MD 24
#define TILE_BLOCKS 4080

// ---------------- scratch (no allocations allowed) ----------------
__device__ float g_lg[BB * H2 * W2];
__device__ float g_rg[BB * H2 * W2];
// accumulators padded to one 128B line each to avoid LTS atomic serialization
// idx: 0 gtNum 1 gtDen 2 photoNum 3 photoDen 4 signSum 5 magSum 6 activeSum 7 smx 8 smy
__device__ double g_acc[9 * 16];
__device__ int g_counter;   // zero-initialized; self-resetting

// ---------------- helpers ----------------
__device__ __forceinline__ float blockReduceSum(float v, float* sbuf) {
    int tid = threadIdx.x + threadIdx.y * blockDim.x;
    int lane = tid & 31, wid = tid >> 5;
#pragma unroll
    for (int o = 16; o > 0; o >>= 1) v += __shfl_down_sync(0xffffffffu, v, o);
    if (lane == 0) sbuf[wid] = v;
    __syncthreads();
    int nw = (blockDim.x * blockDim.y + 31) >> 5;
    v = (tid < nw) ? sbuf[tid] : 0.f;
    if (wid == 0) {
#pragma unroll
        for (int o = 16; o > 0; o >>= 1) v += __shfl_down_sync(0xffffffffu, v, o);
    }
    __syncthreads();
    return v;  // valid at tid 0
}

// ---------------- kernels ----------------
// half-res grayscale + accumulator/counter zeroing (block 0)
__global__ void downsample_kernel(const float* __restrict__ left,
                                  const float* __restrict__ right) {
    if (blockIdx.x == 0) {
        if (threadIdx.x < 9 * 16) g_acc[threadIdx.x] = 0.0;
        if (threadIdx.x == 0) g_counter = 0;
    }
    int i = blockIdx.x * blockDim.x + threadIdx.x;
    const int NPAIR = W2 / 2;  // 240
    if (i >= BB * H2 * NPAIR) return;
    int px = i % NPAIR;
    int y = (i / NPAIR) % H2;
    int b = i / (NPAIR * H2);
    float l0 = 0.f, l1 = 0.f, r0 = 0.f, r1 = 0.f;
#pragma unroll
    for (int c = 0; c < 3; c++) {
        int base = ((b * 3 + c) * HH + 2 * y) * WW + 4 * px;
        float4 a0 = *(const float4*)(left + base);
        float4 a1 = *(const float4*)(left + base + WW);
        l0 += (a0.x + a0.y + a1.x + a1.y);
        l1 += (a0.z + a0.w + a1.z + a1.w);
        float4 b0 = *(const float4*)(right + base);
        float4 b1 = *(const float4*)(right + base + WW);
        r0 += (b0.x + b0.y + b1.x + b1.y);
        r1 += (b0.z + b0.w + b1.z + b1.w);
    }
    const float S = 0.25f / 3.0f;
    int o = (b * H2 + y) * W2 + 2 * px;
    *(float2*)(g_lg + o) = make_float2(l0 * S, l1 * S);
    *(float2*)(g_rg + o) = make_float2(r0 * S, r1 * S);
}

// NCC disparity search + sign/magnitude: one CTA per (b, PAIR of half-res rows),
// 480 threads (one per column). Row y0+1 stats derived from row y0 by register
// rolling. sqrt-free argmax via x|x| monotonicity; sign/mag consumed from
// registers (nc/nd never touch global memory).
__global__ void __launch_bounds__(480, 2) ncc_kernel(const float* __restrict__ pred) {
    __shared__ float rgS[12][528];                        // rows y0-5..y0+6, zero-padded +/-24
    __shared__ float crp0[560], cr2p0[560];               // rg column sums row0 window (idx=x+40)
    __shared__ float crp1[560], cr2p1[560];               // rg column sums row1 window
    __shared__ float Hcr0[528], Hcr20[528];               // 11-box of crp0 at u=idx-24
    __shared__ float Hcr1[528], Hcr21[528];               // 11-box of crp1
    __shared__ float ccS[2][6][496];                      // cross column sums, idx = x+8
    __shared__ float sbuf[16];
    float* clp0 = &ccS[0][0][0];                          // setup-only aliases (560 each)
    float* cl2p0 = clp0 + 560;
    float* clp1 = clp0 + 1120;
    float* cl2p1 = clp0 + 1680;
    const float NORM = 1.0f / 121.0f;

    int pr = blockIdx.x;
    int b = pr / (H2 / 2);
    int yp = pr - b * (H2 / 2);
    int y0 = 2 * yp;
    int x = threadIdx.x;
    const float* lgB = g_lg + b * H2 * W2;
    const float* rgB = g_rg + b * H2 * W2;

    float lgR[12];
    float cr0 = 0.f, cr20 = 0.f, cl0 = 0.f, cl20 = 0.f;
    float rv0 = 0.f, rv11 = 0.f;
#pragma unroll
    for (int r = 0; r < 12; r++) {
        int yy = y0 + r - 5;
        float lv = 0.f, rv = 0.f;
        if (yy >= 0 && yy < H2) { lv = lgB[yy * W2 + x]; rv = rgB[yy * W2 + x]; }
        lgR[r] = lv;
        rgS[r][x + 24] = rv;
        if (x < 24) { rgS[r][x] = 0.f; rgS[r][x + 504] = 0.f; }
        if (r < 11) { cr0 += rv; cr20 += rv * rv; cl0 += lv; cl20 += lv * lv; }
        if (r == 0) rv0 = rv;
        if (r == 11) rv11 = rv;
    }
    float cr1 = cr0 - rv0 + rv11;
    float cr21 = cr20 - rv0 * rv0 + rv11 * rv11;
    float cl1 = cl0 - lgR[0] + lgR[11];
    float cl21 = cl20 - lgR[0] * lgR[0] + lgR[11] * lgR[11];

    crp0[x + 40] = cr0; cr2p0[x + 40] = cr20;
    crp1[x + 40] = cr1; cr2p1[x + 40] = cr21;
    clp0[x + 40] = cl0; cl2p0[x + 40] = cl20;
    clp1[x + 40] = cl1; cl2p1[x + 40] = cl21;
    if (x < 40) {
        crp0[x] = 0.f; cr2p0[x] = 0.f; crp1[x] = 0.f; cr2p1[x] = 0.f;
        clp0[x] = 0.f; cl2p0[x] = 0.f; clp1[x] = 0.f; cl2p1[x] = 0.f;
    }
    if (x >= 440) {
        crp0[x + 80] = 0.f; cr2p0[x + 80] = 0.f; crp1[x + 80] = 0.f; cr2p1[x + 80] = 0.f;
        clp0[x + 80] = 0.f; cl2p0[x + 80] = 0.f; clp1[x + 80] = 0.f; cl2p1[x + 80] = 0.f;
    }
    __syncthreads();

    // Hcr[i] = 11-box of cr centered at col i-24 : taps crp[i+11..i+21]
    for (int i = x; i < 528; i += 480) {
        float s0 = 0.f, s20 = 0.f, s1 = 0.f, s21 = 0.f;
#pragma unroll
        for (int k = 0; k < 11; k++) {
            s0 += crp0[i + 11 + k]; s20 += cr2p0[i + 11 + k];
            s1 += crp1[i + 11 + k]; s21 += cr2p1[i + 11 + k];
        }
        Hcr0[i] = s0; Hcr20[i] = s20; Hcr1[i] = s1; Hcr21[i] = s21;
    }
    // left stats for both rows (variance kept squared: L = ls^2)
    float lm0 = 0.f, lq0 = 0.f, lm1 = 0.f, lq1 = 0.f;
#pragma unroll
    for (int k = 0; k < 11; k++) {
        lm0 += clp0[x + 35 + k]; lq0 += cl2p0[x + 35 + k];
        lm1 += clp1[x + 35 + k]; lq1 += cl2p1[x + 35 + k];
    }
    lm0 *= NORM; lq0 *= NORM; lm1 *= NORM; lq1 *= NORM;
    float L0 = fmaxf(lq0 - lm0 * lm0, 1e-8f);
    float L1 = fmaxf(lq1 - lm1 * lm1, 1e-8f);
    __syncthreads();   // clp reads done; ccS region now free

    // zero ccS pads (idx 0..7, 488..495)
    if (x < 8) {
#pragma unroll
        for (int rr = 0; rr < 2; rr++)
#pragma unroll
            for (int j = 0; j < 6; j++) { ccS[rr][j][x] = 0.f; ccS[rr][j][488 + x] = 0.f; }
    }

    // sqrt-free argmax: value = num/sqrt(A); compare via num|num|*bestA > bestQ*A
    float bestQ0 = -1.f, bestA0 = 1.f, bestN0 = -1.f, bestD0 = 0.f;
    float bestQ1 = -1.f, bestA1 = 1.f, bestN1 = -1.f, bestD1 = 0.f;
    bool interior = (x >= 5 && x < 475);
    for (int g = 0; g < 8; g++) {
        float cc0r[6], cc1r[6];
#pragma unroll
        for (int j = 0; j < 6; j++) {
            int idx = g * 6 + j;
            int d = (idx < 24) ? (idx - 24) : (idx - 23);
            int u = x + d + 24;
            float w0v = rgS[0][u];
            float s = lgR[0] * w0v;
#pragma unroll
            for (int r = 1; r < 11; r++) s += lgR[r] * rgS[r][u];
            cc0r[j] = s;
            float w11v = rgS[11][u];
            cc1r[j] = s - lgR[0] * w0v + lgR[11] * w11v;
            ccS[0][j][x + 8] = s;
            ccS[1][j][x + 8] = cc1r[j];
        }
        __syncthreads();
#pragma unroll
        for (int j = 0; j < 6; j++) {
            int idx = g * 6 + j;
            int d = (idx < 24) ? (idx - 24) : (idx - 23);
            float cross0 = cc0r[j], cross1 = cc1r[j];
#pragma unroll
            for (int k = -5; k < 0; k++) { cross0 += ccS[0][j][x + 8 + k]; cross1 += ccS[1][j][x + 8 + k]; }
#pragma unroll
            for (int k = 1; k <= 5; k++) { cross0 += ccS[0][j][x + 8 + k]; cross1 += ccS[1][j][x + 8 + k]; }
            float rm0_, r20_, rm1_, r21_;
            if (interior) {
                int u = x + d + 24;
                rm0_ = Hcr0[u]; r20_ = Hcr20[u]; rm1_ = Hcr1[u]; r21_ = Hcr21[u];
            } else {
                rm0_ = 0.f; r20_ = 0.f; rm1_ = 0.f; r21_ = 0.f;
#pragma unroll
                for (int k = -5; k <= 5; k++) {
                    int uu = x + k;
                    if (uu >= 0 && uu < W2) {
                        rm0_ += crp0[uu + d + 40]; r20_ += cr2p0[uu + d + 40];
                        rm1_ += crp1[uu + d + 40]; r21_ += cr2p1[uu + d + 40];
                    }
                }
            }
            float rm = rm0_ * NORM;
            float A = L0 * fmaxf(r20_ * NORM - rm * rm, 1e-8f);
            float num = cross0 * NORM - lm0 * rm;
            float q = num * fabsf(num);
            if (q * bestA0 > bestQ0 * A) { bestQ0 = q; bestA0 = A; bestN0 = num; bestD0 = (float)d; }
            rm = rm1_ * NORM;
            A = L1 * fmaxf(r21_ * NORM - rm * rm, 1e-8f);
            num = cross1 * NORM - lm1 * rm;
            q = num * fabsf(num);
            if (q * bestA1 > bestQ1 * A) { bestQ1 = q; bestA1 = A; bestN1 = num; bestD1 = (float)d; }
        }
        __syncthreads();
    }

    // ---- sign/magnitude directly from register-resident (nc, nd) ----
    float nc0 = fmaxf(bestN0 / (sqrtf(bestA0) + 1e-8f), 0.f);
    float nc1 = fmaxf(bestN1 / (sqrtf(bestA1) + 1e-8f), 0.f);
    float sS = 0.f, sM = 0.f, sA = 0.f;
#pragma unroll
    for (int k = 0; k < 2; k++) {
        float ncv = (k == 0) ? nc0 : nc1;
        float ndv = ((k == 0) ? bestD0 : bestD1) * 2.0f;
        if (ncv > 0.3f) {
            float sgn = (ndv > 0.f) ? 1.f : ((ndv < 0.f) ? -1.f : 0.f);
#pragma unroll
            for (int r = 0; r < 2; r++) {
                int row = 2 * (y0 + k) + r;
                float2 p = *(const float2*)(pred + (b * HH + row) * WW + 2 * x);
                sA += 2.f;
                sS += fmaxf(-p.x * sgn, 0.f) + fmaxf(-p.y * sgn, 0.f);
                sM += ncv * (fabsf(p.x - ndv) + fabsf(p.y - ndv));
            }
        }
    }
    float v;
    v = blockReduceSum(sS, sbuf); if (x == 0) atomicAdd(&g_acc[4 * 16], (double)v);
    v = blockReduceSum(sM, sbuf); if (x == 0) atomicAdd(&g_acc[5 * 16], (double)v);
    v = blockReduceSum(sA, sbuf); if (x == 0) atomicAdd(&g_acc[6 * 16], (double)v);
}

// Fused full-res pass: warp-on-the-fly + SSIM/L1 photometric + GT anchor
// + smoothness. 64x8 tiles, 128 threads, 4 outputs/thread. Last block finalizes.
__global__ __launch_bounds__(128) void tile_kernel(const float* __restrict__ pred,
                                                   const float* __restrict__ gt,
                                                   const float* __restrict__ conf,
                                                   const float* __restrict__ occ,
                                                   const float* __restrict__ left,
                                                   const float* __restrict__ right,
                                                   float* __restrict__ out) {
    __shared__ float lS[3][10][66];
    __shared__ float wS[3][10][66];
    __shared__ float dS[10][66];
    __shared__ float sbuf[8];
    __shared__ int lastFlag;
    int b = blockIdx.z;
    int tx0 = blockIdx.x * 64, ty0 = blockIdx.y * 8;
    int tid = threadIdx.y * 16 + threadIdx.x;

    // halo load: compute warped right on the fly
    for (int i = tid; i < 10 * 66; i += 128) {
        int col = i % 66;
        int rrow = i / 66;
        int gx = tx0 + col - 1, gy = ty0 + rrow - 1;
        if (gx >= 0 && gx < WW && gy >= 0 && gy < HH) {
            float disp = pred[(b * HH + gy) * WW + gx];
            dS[rrow][col] = disp;
            float xs = (float)gx - disp;
            float xc = fminf(fmaxf(xs, 0.f), (float)(WW - 1));
            float x0f = floorf(xc);
            float w = xc - x0f;
            int x0i = (int)x0f;
            int x1i = min(x0i + 1, WW - 1);
#pragma unroll
            for (int c = 0; c < 3; c++) {
                const float* R = right + ((b * 3 + c) * HH + gy) * WW;
                wS[c][rrow][col] = R[x0i] * (1.f - w) + R[x1i] * w;
                lS[c][rrow][col] = left[((b * 3 + c) * HH + gy) * WW + gx];
            }
        } else {
            dS[rrow][col] = 0.f;
#pragma unroll
            for (int c = 0; c < 3; c++) { wS[c][rrow][col] = 0.f; lS[c][rrow][col] = 0.f; }
        }
    }
    __syncthreads();

    int tx = threadIdx.x, ty = threadIdx.y;
    int lx0 = 4 * tx;                 // local col of first output
    int gx0 = tx0 + lx0, gy = ty0 + ty;

    float ssAcc[4] = {0, 0, 0, 0}, l1Acc[4] = {0, 0, 0, 0};
    float sidx[4] = {0, 0, 0, 0}, sidy[4] = {0, 0, 0, 0};
    const float N9 = 1.f / 9.f;
    const float C1 = 1e-4f, C2 = 9e-4f;
#pragma unroll
    for (int c = 0; c < 3; c++) {
        float win[4][5];
#pragma unroll
        for (int j = 0; j < 4; j++)
#pragma unroll
            for (int q = 0; q < 5; q++) win[j][q] = 0.f;
        float prev1 = 0.f;
#pragma unroll
        for (int u = 0; u < 6; u++) {
            float l0 = lS[c][ty][lx0 + u], l1 = lS[c][ty + 1][lx0 + u], l2 = lS[c][ty + 2][lx0 + u];
            float m0 = wS[c][ty][lx0 + u], m1 = wS[c][ty + 1][lx0 + u], m2 = wS[c][ty + 2][lx0 + u];
            float cA = l0 + l1 + l2;
            float cB = m0 + m1 + m2;
            float cC = l0 * l0 + l1 * l1 + l2 * l2;
            float cD = m0 * m0 + m1 * m1 + m2 * m2;
            float cE = l0 * m0 + l1 * m1 + l2 * m2;
#pragma unroll
            for (int j = 0; j < 4; j++) {
                if (u >= j && u <= j + 2) {
                    win[j][0] += cA; win[j][1] += cB; win[j][2] += cC;
                    win[j][3] += cD; win[j][4] += cE;
                }
            }
            if (u >= 1 && u <= 4) {
                l1Acc[u - 1] += fabsf(l1 - m1);
                sidy[u - 1] += fabsf(l2 - l1);
            }
            if (u >= 2) sidx[u - 2] += fabsf(l1 - prev1);
            prev1 = l1;
        }
#pragma unroll
        for (int j = 0; j < 4; j++) {
            float mx = win[j][0] * N9, my = win[j][1] * N9;
            float vx = fmaxf(win[j][2] * N9 - mx * mx, 0.f);
            float vy = fmaxf(win[j][3] * N9 - my * my, 0.f);
            float cxy = win[j][4] * N9 - mx * my;
            float nn = (2.f * mx * my + C1) * (2.f * cxy + C2);
            float dd = (mx * mx + my * my + C1) * (vx + vy + C2);
            ssAcc[j] += fminf(fmaxf((1.f - nn / dd) * 0.5f, 0.f), 1.f);
        }
    }

    // per-output remaining terms
    int gi0 = (b * HH + gy) * WW + gx0;
    float4 gtv = *(const float4*)(gt + gi0);
    float4 cfv = *(const float4*)(conf + gi0);
    float4 ocv = *(const float4*)(occ + gi0);
    float gtA[4] = {gtv.x, gtv.y, gtv.z, gtv.w};
    float cfA[4] = {cfv.x, cfv.y, cfv.z, cfv.w};
    float ocA[4] = {ocv.x, ocv.y, ocv.z, ocv.w};

    float s_gtn = 0.f, s_trust = 0.f, s_perr = 0.f, s_valid = 0.f;
    float s_sx = 0.f, s_sy = 0.f;
#pragma unroll
    for (int j = 0; j < 4; j++) {
        int gx = gx0 + j;
        float dcen = dS[ty + 1][lx0 + j + 1];
        float xs = (float)gx - dcen;
        float valid = (xs > 0.f && xs < (float)(WW - 1)) ? 1.f : 0.f;
        float perr = (0.85f * (ssAcc[j] * (1.f / 3.f)) + 0.15f * (l1Acc[j] * (1.f / 3.f))) * valid;
        s_perr += perr; s_valid += valid;

        float g = gtA[j];
        float trust = (g > 2.f) ? cfA[j] * ocA[j] : 0.f;
        s_gtn += trust * fabsf(dcen - g);
        s_trust += trust;

        if (gx < WW - 1) {
            float ddx = fabsf(dS[ty + 1][lx0 + j + 2] - dcen);
            s_sx += ddx * __expf(-sidx[j] * (1.f / 3.f));
        }
        if (gy < HH - 1) {
            float ddy = fabsf(dS[ty + 2][lx0 + j + 1] - dcen);
            s_sy += ddy * __expf(-sidy[j] * (1.f / 3.f));
        }
    }

    __syncthreads();
    float v;
    v = blockReduceSum(s_gtn, sbuf);   if (tid == 0) atomicAdd(&g_acc[0 * 16], (double)v);
    v = blockReduceSum(s_trust, sbuf); if (tid == 0) atomicAdd(&g_acc[1 * 16], (double)v);
    v = blockReduceSum(s_perr, sbuf);  if (tid == 0) atomicAdd(&g_acc[2 * 16], (double)v);
    v = blockReduceSum(s_valid, sbuf); if (tid == 0) atomicAdd(&g_acc[3 * 16], (double)v);
    v = blockReduceSum(s_sx, sbuf);    if (tid == 0) atomicAdd(&g_acc[7 * 16], (double)v);
    v = blockReduceSum(s_sy, sbuf);    if (tid == 0) atomicAdd(&g_acc[8 * 16], (double)v);

    // --- finalize (last block; ncc kernel completed before this kernel began) ---
    if (tid == 0) {
        __threadfence();
        int c = atomicAdd(&g_counter, 1);
        lastFlag = (c == TILE_BLOCKS - 1) ? 1 : 0;
    }
    __syncthreads();
    if (lastFlag && tid == 0) {
        __threadfence();
        double gtl = g_acc[0 * 16] / fmax(g_acc[1 * 16], 1.0);
        double photo = g_acc[2 * 16] / fmax(g_acc[3 * 16], 1.0);
        double n = fmax(g_acc[6 * 16], 1.0);
        double signmag = 0.3 * (g_acc[4 * 16] / n) + 0.7 * (g_acc[5 * 16] / n);
        double smooth = g_acc[7 * 16] / ((double)BB * HH * (WW - 1)) +
                        g_acc[8 * 16] / ((double)BB * (HH - 1) * WW);
        out[0] = (float)(1.0 * gtl + 1.0 * photo + 0.5 * signmag + 0.1 * smooth);
        g_counter = 0;
    }
}

// ---------------- launch ----------------
extern "C" void kernel_launch(void* const* d_in, const int* in_sizes, int n_in,
                              void* d_out, int out_size) {
    const float* pred  = (const float*)d_in[0];
    const float* gt    = (const float*)d_in[1];
    const float* conf  = (const float*)d_in[2];
    const float* occ   = (const float*)d_in[3];
    const float* left  = (const float*)d_in[4];
    const float* right = (const float*)d_in[5];
    float* out = (float*)d_out;

    downsample_kernel<<<(BB * H2 * (W2 / 2) + 255) / 256, 256>>>(left, right);
    ncc_kernel<<<BB * (H2 / 2), 480>>>(pred);
    dim3 tb(16, 8), tg(WW / 64, HH / 8, BB);
    tile_kernel<<<tg, tb>>>(pred, gt, conf, occ, left, right, out);
}

// round 14
// speedup vs baseline: 1.5559x; 1.5559x over previous
#include <cuda_runtime.h>
#include <math.h>

#define BB 4
#define HH 544
#define WW 960
#define H2 272
#define W2 480
#define MD 24
#define TILE_BLOCKS 4080

// ---------------- scratch (no allocations allowed) ----------------
__device__ float g_lg[BB * H2 * W2];
__device__ float g_rg[BB * H2 * W2];
// accumulators padded to one 128B line each to avoid LTS atomic serialization
// idx: 0 gtNum 1 gtDen 2 photoNum 3 photoDen 4 signSum 5 magSum 6 activeSum 7 smx 8 smy
__device__ double g_acc[9 * 16];
__device__ int g_counter;   // zero-initialized; self-resetting

// ---------------- helpers ----------------
__device__ __forceinline__ float blockReduceSum(float v, float* sbuf) {
    int tid = threadIdx.x + threadIdx.y * blockDim.x;
    int lane = tid & 31, wid = tid >> 5;
#pragma unroll
    for (int o = 16; o > 0; o >>= 1) v += __shfl_down_sync(0xffffffffu, v, o);
    if (lane == 0) sbuf[wid] = v;
    __syncthreads();
    int nw = (blockDim.x * blockDim.y + 31) >> 5;
    v = (tid < nw) ? sbuf[tid] : 0.f;
    if (wid == 0) {
#pragma unroll
        for (int o = 16; o > 0; o >>= 1) v += __shfl_down_sync(0xffffffffu, v, o);
    }
    __syncthreads();
    return v;  // valid at tid 0
}

// ---------------- kernels ----------------
// half-res grayscale + accumulator/counter zeroing (block 0)
__global__ void downsample_kernel(const float* __restrict__ left,
                                  const float* __restrict__ right) {
    if (blockIdx.x == 0) {
        if (threadIdx.x < 9 * 16) g_acc[threadIdx.x] = 0.0;
        if (threadIdx.x == 0) g_counter = 0;
    }
    int i = blockIdx.x * blockDim.x + threadIdx.x;
    const int NPAIR = W2 / 2;  // 240
    if (i >= BB * H2 * NPAIR) return;
    int px = i % NPAIR;
    int y = (i / NPAIR) % H2;
    int b = i / (NPAIR * H2);
    float l0 = 0.f, l1 = 0.f, r0 = 0.f, r1 = 0.f;
#pragma unroll
    for (int c = 0; c < 3; c++) {
        int base = ((b * 3 + c) * HH + 2 * y) * WW + 4 * px;
        float4 a0 = *(const float4*)(left + base);
        float4 a1 = *(const float4*)(left + base + WW);
        l0 += (a0.x + a0.y + a1.x + a1.y);
        l1 += (a0.z + a0.w + a1.z + a1.w);
        float4 b0 = *(const float4*)(right + base);
        float4 b1 = *(const float4*)(right + base + WW);
        r0 += (b0.x + b0.y + b1.x + b1.y);
        r1 += (b0.z + b0.w + b1.z + b1.w);
    }
    const float S = 0.25f / 3.0f;
    int o = (b * H2 + y) * W2 + 2 * px;
    *(float2*)(g_lg + o) = make_float2(l0 * S, l1 * S);
    *(float2*)(g_rg + o) = make_float2(r0 * S, r1 * S);
}

// NCC disparity search + sign/magnitude: one CTA per (b, PAIR of half-res rows),
// 480 threads (one per column). Row y0+1 stats derived from row y0 by register
// rolling. Division-free argmax EXACTLY as round 9 (register-ceiling safe);
// sign/mag consumed from registers in the tail (nc/nd never touch global).
__global__ void __launch_bounds__(480, 2) ncc_kernel(const float* __restrict__ pred) {
    __shared__ float rgS[12][528];                        // rows y0-5..y0+6, zero-padded +/-24
    __shared__ float crp0[560], cr2p0[560];               // rg column sums row0 window (idx=x+40)
    __shared__ float crp1[560], cr2p1[560];               // rg column sums row1 window
    __shared__ float Hcr0[528], Hcr20[528];               // 11-box of crp0 at u=idx-24
    __shared__ float Hcr1[528], Hcr21[528];               // 11-box of crp1
    __shared__ float ccS[2][6][496];                      // cross column sums, idx = x+8
    __shared__ float sbuf[16];
    float* clp0 = &ccS[0][0][0];                          // setup-only aliases (560 each)
    float* cl2p0 = clp0 + 560;
    float* clp1 = clp0 + 1120;
    float* cl2p1 = clp0 + 1680;
    const float NORM = 1.0f / 121.0f;

    int pr = blockIdx.x;
    int b = pr / (H2 / 2);
    int yp = pr - b * (H2 / 2);
    int y0 = 2 * yp;
    int x = threadIdx.x;
    const float* lgB = g_lg + b * H2 * W2;
    const float* rgB = g_rg + b * H2 * W2;

    float lgR[12];
    float cr0 = 0.f, cr20 = 0.f, cl0 = 0.f, cl20 = 0.f;
    float rv0 = 0.f, rv11 = 0.f;
#pragma unroll
    for (int r = 0; r < 12; r++) {
        int yy = y0 + r - 5;
        float lv = 0.f, rv = 0.f;
        if (yy >= 0 && yy < H2) { lv = lgB[yy * W2 + x]; rv = rgB[yy * W2 + x]; }
        lgR[r] = lv;
        rgS[r][x + 24] = rv;
        if (x < 24) { rgS[r][x] = 0.f; rgS[r][x + 504] = 0.f; }
        if (r < 11) { cr0 += rv; cr20 += rv * rv; cl0 += lv; cl20 += lv * lv; }
        if (r == 0) rv0 = rv;
        if (r == 11) rv11 = rv;
    }
    float cr1 = cr0 - rv0 + rv11;
    float cr21 = cr20 - rv0 * rv0 + rv11 * rv11;
    float cl1 = cl0 - lgR[0] + lgR[11];
    float cl21 = cl20 - lgR[0] * lgR[0] + lgR[11] * lgR[11];

    crp0[x + 40] = cr0; cr2p0[x + 40] = cr20;
    crp1[x + 40] = cr1; cr2p1[x + 40] = cr21;
    clp0[x + 40] = cl0; cl2p0[x + 40] = cl20;
    clp1[x + 40] = cl1; cl2p1[x + 40] = cl21;
    if (x < 40) {
        crp0[x] = 0.f; cr2p0[x] = 0.f; crp1[x] = 0.f; cr2p1[x] = 0.f;
        clp0[x] = 0.f; cl2p0[x] = 0.f; clp1[x] = 0.f; cl2p1[x] = 0.f;
    }
    if (x >= 440) {
        crp0[x + 80] = 0.f; cr2p0[x + 80] = 0.f; crp1[x + 80] = 0.f; cr2p1[x + 80] = 0.f;
        clp0[x + 80] = 0.f; cl2p0[x + 80] = 0.f; clp1[x + 80] = 0.f; cl2p1[x + 80] = 0.f;
    }
    __syncthreads();

    // Hcr[i] = 11-box of cr centered at col i-24 : taps crp[i+11..i+21]
    for (int i = x; i < 528; i += 480) {
        float s0 = 0.f, s20 = 0.f, s1 = 0.f, s21 = 0.f;
#pragma unroll
        for (int k = 0; k < 11; k++) {
            s0 += crp0[i + 11 + k]; s20 += cr2p0[i + 11 + k];
            s1 += crp1[i + 11 + k]; s21 += cr2p1[i + 11 + k];
        }
        Hcr0[i] = s0; Hcr20[i] = s20; Hcr1[i] = s1; Hcr21[i] = s21;
    }
    // left stats for both rows
    float lm0 = 0.f, lq0 = 0.f, lm1 = 0.f, lq1 = 0.f;
#pragma unroll
    for (int k = 0; k < 11; k++) {
        lm0 += clp0[x + 35 + k]; lq0 += cl2p0[x + 35 + k];
        lm1 += clp1[x + 35 + k]; lq1 += cl2p1[x + 35 + k];
    }
    lm0 *= NORM; lq0 *= NORM; lm1 *= NORM; lq1 *= NORM;
    float ls0 = sqrtf(fmaxf(lq0 - lm0 * lm0, 1e-8f));
    float ls1 = sqrtf(fmaxf(lq1 - lm1 * lm1, 1e-8f));
    __syncthreads();   // clp reads done; ccS region now free

    // zero ccS pads (idx 0..7, 488..495) — disjoint from data writes below
    if (x < 8) {
#pragma unroll
        for (int rr = 0; rr < 2; rr++)
#pragma unroll
            for (int j = 0; j < 6; j++) { ccS[rr][j][x] = 0.f; ccS[rr][j][488 + x] = 0.f; }
    }

    // division-free argmax state: best = bestNum/bestDen, bestDen > 0 always
    float bestN0 = -1.f, bestDen0 = 1.f, bestD0 = 0.f;
    float bestN1 = -1.f, bestDen1 = 1.f, bestD1 = 0.f;
    bool interior = (x >= 5 && x < 475);
    for (int g = 0; g < 8; g++) {
        float cc0r[6], cc1r[6];
#pragma unroll
        for (int j = 0; j < 6; j++) {
            int idx = g * 6 + j;
            int d = (idx < 24) ? (idx - 24) : (idx - 23);
            int u = x + d + 24;
            float w0v = rgS[0][u];
            float s = lgR[0] * w0v;
#pragma unroll
            for (int r = 1; r < 11; r++) s += lgR[r] * rgS[r][u];
            cc0r[j] = s;
            float w11v = rgS[11][u];
            cc1r[j] = s - lgR[0] * w0v + lgR[11] * w11v;
            ccS[0][j][x + 8] = s;
            ccS[1][j][x + 8] = cc1r[j];
        }
        __syncthreads();
#pragma unroll
        for (int j = 0; j < 6; j++) {
            int idx = g * 6 + j;
            int d = (idx < 24) ? (idx - 24) : (idx - 23);
            // cross boxes: own column kept in register (10 taps each)
            float cross0 = cc0r[j], cross1 = cc1r[j];
#pragma unroll
            for (int k = -5; k < 0; k++) { cross0 += ccS[0][j][x + 8 + k]; cross1 += ccS[1][j][x + 8 + k]; }
#pragma unroll
            for (int k = 1; k <= 5; k++) { cross0 += ccS[0][j][x + 8 + k]; cross1 += ccS[1][j][x + 8 + k]; }
            float rm0_, r20_, rm1_, r21_;
            if (interior) {
                int u = x + d + 24;
                rm0_ = Hcr0[u]; r20_ = Hcr20[u]; rm1_ = Hcr1[u]; r21_ = Hcr21[u];
            } else {
                rm0_ = 0.f; r20_ = 0.f; rm1_ = 0.f; r21_ = 0.f;
#pragma unroll
                for (int k = -5; k <= 5; k++) {
                    int uu = x + k;
                    if (uu >= 0 && uu < W2) {
                        rm0_ += crp0[uu + d + 40]; r20_ += cr2p0[uu + d + 40];
                        rm1_ += crp1[uu + d + 40]; r21_ += cr2p1[uu + d + 40];
                    }
                }
            }
            float rm = rm0_ * NORM;
            float rstd = sqrtf(fmaxf(r20_ * NORM - rm * rm, 1e-8f));
            float num = cross0 * NORM - lm0 * rm;
            float den = ls0 * rstd + 1e-8f;
            if (num * bestDen0 > bestN0 * den) { bestN0 = num; bestDen0 = den; bestD0 = (float)d; }
            rm = rm1_ * NORM;
            rstd = sqrtf(fmaxf(r21_ * NORM - rm * rm, 1e-8f));
            num = cross1 * NORM - lm1 * rm;
            den = ls1 * rstd + 1e-8f;
            if (num * bestDen1 > bestN1 * den) { bestN1 = num; bestDen1 = den; bestD1 = (float)d; }
        }
        __syncthreads();
    }

    // ---- sign/magnitude tail: all inputs already live; adds no in-loop pressure ----
    float nc0 = fmaxf(bestN0 / bestDen0, 0.f);
    float nc1 = fmaxf(bestN1 / bestDen1, 0.f);
    float sS = 0.f, sM = 0.f, sA = 0.f;
#pragma unroll
    for (int k = 0; k < 2; k++) {
        float ncv = (k == 0) ? nc0 : nc1;
        float ndv = ((k == 0) ? bestD0 : bestD1) * 2.0f;
        if (ncv > 0.3f) {
            float sgn = (ndv > 0.f) ? 1.f : ((ndv < 0.f) ? -1.f : 0.f);
#pragma unroll
            for (int r = 0; r < 2; r++) {
                int row = 2 * (y0 + k) + r;
                float2 p = *(const float2*)(pred + (b * HH + row) * WW + 2 * x);
                sA += 2.f;
                sS += fmaxf(-p.x * sgn, 0.f) + fmaxf(-p.y * sgn, 0.f);
                sM += ncv * (fabsf(p.x - ndv) + fabsf(p.y - ndv));
            }
        }
    }
    float v;
    v = blockReduceSum(sS, sbuf); if (x == 0) atomicAdd(&g_acc[4 * 16], (double)v);
    v = blockReduceSum(sM, sbuf); if (x == 0) atomicAdd(&g_acc[5 * 16], (double)v);
    v = blockReduceSum(sA, sbuf); if (x == 0) atomicAdd(&g_acc[6 * 16], (double)v);
}

// Fused full-res pass: warp-on-the-fly + SSIM/L1 photometric + GT anchor
// + smoothness. 64x8 tiles, 128 threads, 4 outputs/thread. Last block finalizes.
__global__ __launch_bounds__(128) void tile_kernel(const float* __restrict__ pred,
                                                   const float* __restrict__ gt,
                                                   const float* __restrict__ conf,
                                                   const float* __restrict__ occ,
                                                   const float* __restrict__ left,
                                                   const float* __restrict__ right,
                                                   float* __restrict__ out) {
    __shared__ float lS[3][10][66];
    __shared__ float wS[3][10][66];
    __shared__ float dS[10][66];
    __shared__ float sbuf[8];
    __shared__ int lastFlag;
    int b = blockIdx.z;
    int tx0 = blockIdx.x * 64, ty0 = blockIdx.y * 8;
    int tid = threadIdx.y * 16 + threadIdx.x;

    // halo load: compute warped right on the fly
    for (int i = tid; i < 10 * 66; i += 128) {
        int col = i % 66;
        int rrow = i / 66;
        int gx = tx0 + col - 1, gy = ty0 + rrow - 1;
        if (gx >= 0 && gx < WW && gy >= 0 && gy < HH) {
            float disp = pred[(b * HH + gy) * WW + gx];
            dS[rrow][col] = disp;
            float xs = (float)gx - disp;
            float xc = fminf(fmaxf(xs, 0.f), (float)(WW - 1));
            float x0f = floorf(xc);
            float w = xc - x0f;
            int x0i = (int)x0f;
            int x1i = min(x0i + 1, WW - 1);
#pragma unroll
            for (int c = 0; c < 3; c++) {
                const float* R = right + ((b * 3 + c) * HH + gy) * WW;
                wS[c][rrow][col] = R[x0i] * (1.f - w) + R[x1i] * w;
                lS[c][rrow][col] = left[((b * 3 + c) * HH + gy) * WW + gx];
            }
        } else {
            dS[rrow][col] = 0.f;
#pragma unroll
            for (int c = 0; c < 3; c++) { wS[c][rrow][col] = 0.f; lS[c][rrow][col] = 0.f; }
        }
    }
    __syncthreads();

    int tx = threadIdx.x, ty = threadIdx.y;
    int lx0 = 4 * tx;                 // local col of first output
    int gx0 = tx0 + lx0, gy = ty0 + ty;

    float ssAcc[4] = {0, 0, 0, 0}, l1Acc[4] = {0, 0, 0, 0};
    float sidx[4] = {0, 0, 0, 0}, sidy[4] = {0, 0, 0, 0};
    const float N9 = 1.f / 9.f;
    const float C1 = 1e-4f, C2 = 9e-4f;
#pragma unroll
    for (int c = 0; c < 3; c++) {
        float win[4][5];
#pragma unroll
        for (int j = 0; j < 4; j++)
#pragma unroll
            for (int q = 0; q < 5; q++) win[j][q] = 0.f;
        float prev1 = 0.f;
#pragma unroll
        for (int u = 0; u < 6; u++) {
            float l0 = lS[c][ty][lx0 + u], l1 = lS[c][ty + 1][lx0 + u], l2 = lS[c][ty + 2][lx0 + u];
            float m0 = wS[c][ty][lx0 + u], m1 = wS[c][ty + 1][lx0 + u], m2 = wS[c][ty + 2][lx0 + u];
            float cA = l0 + l1 + l2;
            float cB = m0 + m1 + m2;
            float cC = l0 * l0 + l1 * l1 + l2 * l2;
            float cD = m0 * m0 + m1 * m1 + m2 * m2;
            float cE = l0 * m0 + l1 * m1 + l2 * m2;
#pragma unroll
            for (int j = 0; j < 4; j++) {
                if (u >= j && u <= j + 2) {
                    win[j][0] += cA; win[j][1] += cB; win[j][2] += cC;
                    win[j][3] += cD; win[j][4] += cE;
                }
            }
            if (u >= 1 && u <= 4) {
                l1Acc[u - 1] += fabsf(l1 - m1);
                sidy[u - 1] += fabsf(l2 - l1);
            }
            if (u >= 2) sidx[u - 2] += fabsf(l1 - prev1);
            prev1 = l1;
        }
#pragma unroll
        for (int j = 0; j < 4; j++) {
            float mx = win[j][0] * N9, my = win[j][1] * N9;
            float vx = fmaxf(win[j][2] * N9 - mx * mx, 0.f);
            float vy = fmaxf(win[j][3] * N9 - my * my, 0.f);
            float cxy = win[j][4] * N9 - mx * my;
            float nn = (2.f * mx * my + C1) * (2.f * cxy + C2);
            float dd = (mx * mx + my * my + C1) * (vx + vy + C2);
            ssAcc[j] += fminf(fmaxf((1.f - nn / dd) * 0.5f, 0.f), 1.f);
        }
    }

    // per-output remaining terms
    int gi0 = (b * HH + gy) * WW + gx0;
    float4 gtv = *(const float4*)(gt + gi0);
    float4 cfv = *(const float4*)(conf + gi0);
    float4 ocv = *(const float4*)(occ + gi0);
    float gtA[4] = {gtv.x, gtv.y, gtv.z, gtv.w};
    float cfA[4] = {cfv.x, cfv.y, cfv.z, cfv.w};
    float ocA[4] = {ocv.x, ocv.y, ocv.z, ocv.w};

    float s_gtn = 0.f, s_trust = 0.f, s_perr = 0.f, s_valid = 0.f;
    float s_sx = 0.f, s_sy = 0.f;
#pragma unroll
    for (int j = 0; j < 4; j++) {
        int gx = gx0 + j;
        float dcen = dS[ty + 1][lx0 + j + 1];
        float xs = (float)gx - dcen;
        float valid = (xs > 0.f && xs < (float)(WW - 1)) ? 1.f : 0.f;
        float perr = (0.85f * (ssAcc[j] * (1.f / 3.f)) + 0.15f * (l1Acc[j] * (1.f / 3.f))) * valid;
        s_perr += perr; s_valid += valid;

        float g = gtA[j];
        float trust = (g > 2.f) ? cfA[j] * ocA[j] : 0.f;
        s_gtn += trust * fabsf(dcen - g);
        s_trust += trust;

        if (gx < WW - 1) {
            float ddx = fabsf(dS[ty + 1][lx0 + j + 2] - dcen);
            s_sx += ddx * __expf(-sidx[j] * (1.f / 3.f));
        }
        if (gy < HH - 1) {
            float ddy = fabsf(dS[ty + 2][lx0 + j + 1] - dcen);
            s_sy += ddy * __expf(-sidy[j] * (1.f / 3.f));
        }
    }

    __syncthreads();
    float v;
    v = blockReduceSum(s_gtn, sbuf);   if (tid == 0) atomicAdd(&g_acc[0 * 16], (double)v);
    v = blockReduceSum(s_trust, sbuf); if (tid == 0) atomicAdd(&g_acc[1 * 16], (double)v);
    v = blockReduceSum(s_perr, sbuf);  if (tid == 0) atomicAdd(&g_acc[2 * 16], (double)v);
    v = blockReduceSum(s_valid, sbuf); if (tid == 0) atomicAdd(&g_acc[3 * 16], (double)v);
    v = blockReduceSum(s_sx, sbuf);    if (tid == 0) atomicAdd(&g_acc[7 * 16], (double)v);
    v = blockReduceSum(s_sy, sbuf);    if (tid == 0) atomicAdd(&g_acc[8 * 16], (double)v);

    // --- finalize (last block; ncc kernel completed before this kernel began) ---
    if (tid == 0) {
        __threadfence();
        int c = atomicAdd(&g_counter, 1);
        lastFlag = (c == TILE_BLOCKS - 1) ? 1 : 0;
    }
    __syncthreads();
    if (lastFlag && tid == 0) {
        __threadfence();
        double gtl = g_acc[0 * 16] / fmax(g_acc[1 * 16], 1.0);
        double photo = g_acc[2 * 16] / fmax(g_acc[3 * 16], 1.0);
        double n = fmax(g_acc[6 * 16], 1.0);
        double signmag = 0.3 * (g_acc[4 * 16] / n) + 0.7 * (g_acc[5 * 16] / n);
        double smooth = g_acc[7 * 16] / ((double)BB * HH * (WW - 1)) +
                        g_acc[8 * 16] / ((double)BB * (HH - 1) * WW);
        out[0] = (float)(1.0 * gtl + 1.0 * photo + 0.5 * signmag + 0.1 * smooth);
        g_counter = 0;
    }
}

// ---------------- launch ----------------
extern "C" void kernel_launch(void* const* d_in, const int* in_sizes, int n_in,
                              void* d_out, int out_size) {
    const float* pred  = (const float*)d_in[0];
    const float* gt    = (const float*)d_in[1];
    const float* conf  = (const float*)d_in[2];
    const float* occ   = (const float*)d_in[3];
    const float* left  = (const float*)d_in[4];
    const float* right = (const float*)d_in[5];
    float* out = (float*)d_out;

    downsample_kernel<<<(BB * H2 * (W2 / 2) + 255) / 256, 256>>>(left, right);
    ncc_kernel<<<BB * (H2 / 2), 480>>>(pred);
    dim3 tb(16, 8), tg(WW / 64, HH / 8, BB);
    tile_kernel<<<tg, tb>>>(pred, gt, conf, occ, left, right, out);
}

// round 15
// speedup vs baseline: 1.7152x; 1.1024x over previous
#include <cuda_runtime.h>
#include <math.h>

#define BB 4
#define HH 544
#define WW 960
#define H2 272
#define W2 480
#define MD 24
#define SM_BLOCKS 2040   // (BB*H2*W2)/256

// ---------------- scratch (no allocations allowed) ----------------
__device__ float g_lg[BB * H2 * W2];
__device__ float g_rg[BB * H2 * W2];
__device__ float g_nd[BB * H2 * W2];
__device__ float g_nc[BB * H2 * W2];
// accumulators padded to one 128B line each to avoid LTS atomic serialization
// idx: 0 gtNum 1 gtDen 2 photoNum 3 photoDen 4 signSum 5 magSum 6 activeSum 7 smx 8 smy
__device__ double g_acc[9 * 16];
__device__ int g_counter;   // zero-initialized; self-resetting

// ---------------- helpers ----------------
__device__ __forceinline__ float blockReduceSum(float v, float* sbuf) {
    int tid = threadIdx.x + threadIdx.y * blockDim.x;
    int lane = tid & 31, wid = tid >> 5;
#pragma unroll
    for (int o = 16; o > 0; o >>= 1) v += __shfl_down_sync(0xffffffffu, v, o);
    if (lane == 0) sbuf[wid] = v;
    __syncthreads();
    int nw = (blockDim.x * blockDim.y + 31) >> 5;
    v = (tid < nw) ? sbuf[tid] : 0.f;
    if (wid == 0) {
#pragma unroll
        for (int o = 16; o > 0; o >>= 1) v += __shfl_down_sync(0xffffffffu, v, o);
    }
    __syncthreads();
    return v;  // valid at tid 0
}

// ---------------- kernels ----------------
// half-res grayscale + accumulator/counter zeroing (block 0)
__global__ void downsample_kernel(const float* __restrict__ left,
                                  const float* __restrict__ right) {
    if (blockIdx.x == 0) {
        if (threadIdx.x < 9 * 16) g_acc[threadIdx.x] = 0.0;
        if (threadIdx.x == 0) g_counter = 0;
    }
    int i = blockIdx.x * blockDim.x + threadIdx.x;
    const int NPAIR = W2 / 2;  // 240
    if (i >= BB * H2 * NPAIR) return;
    int px = i % NPAIR;
    int y = (i / NPAIR) % H2;
    int b = i / (NPAIR * H2);
    float l0 = 0.f, l1 = 0.f, r0 = 0.f, r1 = 0.f;
#pragma unroll
    for (int c = 0; c < 3; c++) {
        int base = ((b * 3 + c) * HH + 2 * y) * WW + 4 * px;
        float4 a0 = *(const float4*)(left + base);
        float4 a1 = *(const float4*)(left + base + WW);
        l0 += (a0.x + a0.y + a1.x + a1.y);
        l1 += (a0.z + a0.w + a1.z + a1.w);
        float4 b0 = *(const float4*)(right + base);
        float4 b1 = *(const float4*)(right + base + WW);
        r0 += (b0.x + b0.y + b1.x + b1.y);
        r1 += (b0.z + b0.w + b1.z + b1.w);
    }
    const float S = 0.25f / 3.0f;
    int o = (b * H2 + y) * W2 + 2 * px;
    *(float2*)(g_lg + o) = make_float2(l0 * S, l1 * S);
    *(float2*)(g_rg + o) = make_float2(r0 * S, r1 * S);
}

// NCC disparity search: EXACT round-9 version (proven local optimum).
// One CTA per (b, PAIR of half-res rows), 480 threads. Row y0+1 stats by
// register rolling; division-free argmax.
__global__ void __launch_bounds__(480, 2) ncc_kernel() {
    __shared__ float rgS[12][528];                        // rows y0-5..y0+6, zero-padded +/-24
    __shared__ float crp0[560], cr2p0[560];               // rg column sums row0 window (idx=x+40)
    __shared__ float crp1[560], cr2p1[560];               // rg column sums row1 window
    __shared__ float Hcr0[528], Hcr20[528];               // 11-box of crp0 at u=idx-24
    __shared__ float Hcr1[528], Hcr21[528];               // 11-box of crp1
    __shared__ float ccS[2][6][496];                      // cross column sums, idx = x+8
    float* clp0 = &ccS[0][0][0];                          // setup-only aliases (560 each)
    float* cl2p0 = clp0 + 560;
    float* clp1 = clp0 + 1120;
    float* cl2p1 = clp0 + 1680;
    const float NORM = 1.0f / 121.0f;

    int pr = blockIdx.x;
    int b = pr / (H2 / 2);
    int yp = pr - b * (H2 / 2);
    int y0 = 2 * yp;
    int x = threadIdx.x;
    const float* lgB = g_lg + b * H2 * W2;
    const float* rgB = g_rg + b * H2 * W2;

    float lgR[12];
    float cr0 = 0.f, cr20 = 0.f, cl0 = 0.f, cl20 = 0.f;
    float rv0 = 0.f, rv11 = 0.f;
#pragma unroll
    for (int r = 0; r < 12; r++) {
        int yy = y0 + r - 5;
        float lv = 0.f, rv = 0.f;
        if (yy >= 0 && yy < H2) { lv = lgB[yy * W2 + x]; rv = rgB[yy * W2 + x]; }
        lgR[r] = lv;
        rgS[r][x + 24] = rv;
        if (x < 24) { rgS[r][x] = 0.f; rgS[r][x + 504] = 0.f; }
        if (r < 11) { cr0 += rv; cr20 += rv * rv; cl0 += lv; cl20 += lv * lv; }
        if (r == 0) rv0 = rv;
        if (r == 11) rv11 = rv;
    }
    float cr1 = cr0 - rv0 + rv11;
    float cr21 = cr20 - rv0 * rv0 + rv11 * rv11;
    float cl1 = cl0 - lgR[0] + lgR[11];
    float cl21 = cl20 - lgR[0] * lgR[0] + lgR[11] * lgR[11];

    crp0[x + 40] = cr0; cr2p0[x + 40] = cr20;
    crp1[x + 40] = cr1; cr2p1[x + 40] = cr21;
    clp0[x + 40] = cl0; cl2p0[x + 40] = cl20;
    clp1[x + 40] = cl1; cl2p1[x + 40] = cl21;
    if (x < 40) {
        crp0[x] = 0.f; cr2p0[x] = 0.f; crp1[x] = 0.f; cr2p1[x] = 0.f;
        clp0[x] = 0.f; cl2p0[x] = 0.f; clp1[x] = 0.f; cl2p1[x] = 0.f;
    }
    if (x >= 440) {
        crp0[x + 80] = 0.f; cr2p0[x + 80] = 0.f; crp1[x + 80] = 0.f; cr2p1[x + 80] = 0.f;
        clp0[x + 80] = 0.f; cl2p0[x + 80] = 0.f; clp1[x + 80] = 0.f; cl2p1[x + 80] = 0.f;
    }
    __syncthreads();

    // Hcr[i] = 11-box of cr centered at col i-24 : taps crp[i+11..i+21]
    for (int i = x; i < 528; i += 480) {
        float s0 = 0.f, s20 = 0.f, s1 = 0.f, s21 = 0.f;
#pragma unroll
        for (int k = 0; k < 11; k++) {
            s0 += crp0[i + 11 + k]; s20 += cr2p0[i + 11 + k];
            s1 += crp1[i + 11 + k]; s21 += cr2p1[i + 11 + k];
        }
        Hcr0[i] = s0; Hcr20[i] = s20; Hcr1[i] = s1; Hcr21[i] = s21;
    }
    // left stats for both rows
    float lm0 = 0.f, lq0 = 0.f, lm1 = 0.f, lq1 = 0.f;
#pragma unroll
    for (int k = 0; k < 11; k++) {
        lm0 += clp0[x + 35 + k]; lq0 += cl2p0[x + 35 + k];
        lm1 += clp1[x + 35 + k]; lq1 += cl2p1[x + 35 + k];
    }
    lm0 *= NORM; lq0 *= NORM; lm1 *= NORM; lq1 *= NORM;
    float ls0 = sqrtf(fmaxf(lq0 - lm0 * lm0, 1e-8f));
    float ls1 = sqrtf(fmaxf(lq1 - lm1 * lm1, 1e-8f));
    __syncthreads();   // clp reads done; ccS region now free

    // zero ccS pads (idx 0..7, 488..495)
    if (x < 8) {
#pragma unroll
        for (int rr = 0; rr < 2; rr++)
#pragma unroll
            for (int j = 0; j < 6; j++) { ccS[rr][j][x] = 0.f; ccS[rr][j][488 + x] = 0.f; }
    }

    // division-free argmax state: best = bestNum/bestDen, bestDen > 0 always
    float bestN0 = -1.f, bestDen0 = 1.f, bestD0 = 0.f;
    float bestN1 = -1.f, bestDen1 = 1.f, bestD1 = 0.f;
    bool interior = (x >= 5 && x < 475);
    for (int g = 0; g < 8; g++) {
        float cc0r[6], cc1r[6];
#pragma unroll
        for (int j = 0; j < 6; j++) {
            int idx = g * 6 + j;
            int d = (idx < 24) ? (idx - 24) : (idx - 23);
            int u = x + d + 24;
            float w0v = rgS[0][u];
            float s = lgR[0] * w0v;
#pragma unroll
            for (int r = 1; r < 11; r++) s += lgR[r] * rgS[r][u];
            cc0r[j] = s;
            float w11v = rgS[11][u];
            cc1r[j] = s - lgR[0] * w0v + lgR[11] * w11v;
            ccS[0][j][x + 8] = s;
            ccS[1][j][x + 8] = cc1r[j];
        }
        __syncthreads();
#pragma unroll
        for (int j = 0; j < 6; j++) {
            int idx = g * 6 + j;
            int d = (idx < 24) ? (idx - 24) : (idx - 23);
            // cross boxes: own column kept in register (10 taps each)
            float cross0 = cc0r[j], cross1 = cc1r[j];
#pragma unroll
            for (int k = -5; k < 0; k++) { cross0 += ccS[0][j][x + 8 + k]; cross1 += ccS[1][j][x + 8 + k]; }
#pragma unroll
            for (int k = 1; k <= 5; k++) { cross0 += ccS[0][j][x + 8 + k]; cross1 += ccS[1][j][x + 8 + k]; }
            float rm0_, r20_, rm1_, r21_;
            if (interior) {
                int u = x + d + 24;
                rm0_ = Hcr0[u]; r20_ = Hcr20[u]; rm1_ = Hcr1[u]; r21_ = Hcr21[u];
            } else {
                rm0_ = 0.f; r20_ = 0.f; rm1_ = 0.f; r21_ = 0.f;
#pragma unroll
                for (int k = -5; k <= 5; k++) {
                    int uu = x + k;
                    if (uu >= 0 && uu < W2) {
                        rm0_ += crp0[uu + d + 40]; r20_ += cr2p0[uu + d + 40];
                        rm1_ += crp1[uu + d + 40]; r21_ += cr2p1[uu + d + 40];
                    }
                }
            }
            float rm = rm0_ * NORM;
            float rstd = sqrtf(fmaxf(r20_ * NORM - rm * rm, 1e-8f));
            float num = cross0 * NORM - lm0 * rm;
            float den = ls0 * rstd + 1e-8f;
            if (num * bestDen0 > bestN0 * den) { bestN0 = num; bestDen0 = den; bestD0 = (float)d; }
            rm = rm1_ * NORM;
            rstd = sqrtf(fmaxf(r21_ * NORM - rm * rm, 1e-8f));
            num = cross1 * NORM - lm1 * rm;
            den = ls1 * rstd + 1e-8f;
            if (num * bestDen1 > bestN1 * den) { bestN1 = num; bestDen1 = den; bestD1 = (float)d; }
        }
        __syncthreads();
    }
    int o = (b * H2 + y0) * W2 + x;
    g_nd[o] = bestD0 * 2.0f;
    g_nc[o] = fmaxf(bestN0 / bestDen0, 0.f);
    g_nd[o + W2] = bestD1 * 2.0f;
    g_nc[o + W2] = fmaxf(bestN1 / bestDen1, 0.f);
}

// Photometric + GT anchor + smoothness ONLY (independent of ncc -> runs
// concurrently with it on a forked stream). 64x8 tiles, 128 threads,
// 4 outputs/thread.
__global__ __launch_bounds__(128) void tileA_kernel(const float* __restrict__ pred,
                                                    const float* __restrict__ gt,
                                                    const float* __restrict__ conf,
                                                    const float* __restrict__ occ,
                                                    const float* __restrict__ left,
                                                    const float* __restrict__ right) {
    __shared__ float lS[3][10][66];
    __shared__ float wS[3][10][66];
    __shared__ float dS[10][66];
    __shared__ float sbuf[8];
    int b = blockIdx.z;
    int tx0 = blockIdx.x * 64, ty0 = blockIdx.y * 8;
    int tid = threadIdx.y * 16 + threadIdx.x;

    // halo load: compute warped right on the fly
    for (int i = tid; i < 10 * 66; i += 128) {
        int col = i % 66;
        int rrow = i / 66;
        int gx = tx0 + col - 1, gy = ty0 + rrow - 1;
        if (gx >= 0 && gx < WW && gy >= 0 && gy < HH) {
            float disp = pred[(b * HH + gy) * WW + gx];
            dS[rrow][col] = disp;
            float xs = (float)gx - disp;
            float xc = fminf(fmaxf(xs, 0.f), (float)(WW - 1));
            float x0f = floorf(xc);
            float w = xc - x0f;
            int x0i = (int)x0f;
            int x1i = min(x0i + 1, WW - 1);
#pragma unroll
            for (int c = 0; c < 3; c++) {
                const float* R = right + ((b * 3 + c) * HH + gy) * WW;
                wS[c][rrow][col] = R[x0i] * (1.f - w) + R[x1i] * w;
                lS[c][rrow][col] = left[((b * 3 + c) * HH + gy) * WW + gx];
            }
        } else {
            dS[rrow][col] = 0.f;
#pragma unroll
            for (int c = 0; c < 3; c++) { wS[c][rrow][col] = 0.f; lS[c][rrow][col] = 0.f; }
        }
    }
    __syncthreads();

    int tx = threadIdx.x, ty = threadIdx.y;
    int lx0 = 4 * tx;                 // local col of first output
    int gx0 = tx0 + lx0, gy = ty0 + ty;

    float ssAcc[4] = {0, 0, 0, 0}, l1Acc[4] = {0, 0, 0, 0};
    float sidx[4] = {0, 0, 0, 0}, sidy[4] = {0, 0, 0, 0};
    const float N9 = 1.f / 9.f;
    const float C1 = 1e-4f, C2 = 9e-4f;
#pragma unroll
    for (int c = 0; c < 3; c++) {
        float win[4][5];
#pragma unroll
        for (int j = 0; j < 4; j++)
#pragma unroll
            for (int q = 0; q < 5; q++) win[j][q] = 0.f;
        float prev1 = 0.f;
#pragma unroll
        for (int u = 0; u < 6; u++) {
            float l0 = lS[c][ty][lx0 + u], l1 = lS[c][ty + 1][lx0 + u], l2 = lS[c][ty + 2][lx0 + u];
            float m0 = wS[c][ty][lx0 + u], m1 = wS[c][ty + 1][lx0 + u], m2 = wS[c][ty + 2][lx0 + u];
            float cA = l0 + l1 + l2;
            float cB = m0 + m1 + m2;
            float cC = l0 * l0 + l1 * l1 + l2 * l2;
            float cD = m0 * m0 + m1 * m1 + m2 * m2;
            float cE = l0 * m0 + l1 * m1 + l2 * m2;
#pragma unroll
            for (int j = 0; j < 4; j++) {
                if (u >= j && u <= j + 2) {
                    win[j][0] += cA; win[j][1] += cB; win[j][2] += cC;
                    win[j][3] += cD; win[j][4] += cE;
                }
            }
            if (u >= 1 && u <= 4) {
                l1Acc[u - 1] += fabsf(l1 - m1);
                sidy[u - 1] += fabsf(l2 - l1);
            }
            if (u >= 2) sidx[u - 2] += fabsf(l1 - prev1);
            prev1 = l1;
        }
#pragma unroll
        for (int j = 0; j < 4; j++) {
            float mx = win[j][0] * N9, my = win[j][1] * N9;
            float vx = fmaxf(win[j][2] * N9 - mx * mx, 0.f);
            float vy = fmaxf(win[j][3] * N9 - my * my, 0.f);
            float cxy = win[j][4] * N9 - mx * my;
            float nn = (2.f * mx * my + C1) * (2.f * cxy + C2);
            float dd = (mx * mx + my * my + C1) * (vx + vy + C2);
            ssAcc[j] += fminf(fmaxf((1.f - nn / dd) * 0.5f, 0.f), 1.f);
        }
    }

    int gi0 = (b * HH + gy) * WW + gx0;
    float4 gtv = *(const float4*)(gt + gi0);
    float4 cfv = *(const float4*)(conf + gi0);
    float4 ocv = *(const float4*)(occ + gi0);
    float gtA[4] = {gtv.x, gtv.y, gtv.z, gtv.w};
    float cfA[4] = {cfv.x, cfv.y, cfv.z, cfv.w};
    float ocA[4] = {ocv.x, ocv.y, ocv.z, ocv.w};

    float s_gtn = 0.f, s_trust = 0.f, s_perr = 0.f, s_valid = 0.f;
    float s_sx = 0.f, s_sy = 0.f;
#pragma unroll
    for (int j = 0; j < 4; j++) {
        int gx = gx0 + j;
        float dcen = dS[ty + 1][lx0 + j + 1];
        float xs = (float)gx - dcen;
        float valid = (xs > 0.f && xs < (float)(WW - 1)) ? 1.f : 0.f;
        float perr = (0.85f * (ssAcc[j] * (1.f / 3.f)) + 0.15f * (l1Acc[j] * (1.f / 3.f))) * valid;
        s_perr += perr; s_valid += valid;

        float g = gtA[j];
        float trust = (g > 2.f) ? cfA[j] * ocA[j] : 0.f;
        s_gtn += trust * fabsf(dcen - g);
        s_trust += trust;

        if (gx < WW - 1) {
            float ddx = fabsf(dS[ty + 1][lx0 + j + 2] - dcen);
            s_sx += ddx * __expf(-sidx[j] * (1.f / 3.f));
        }
        if (gy < HH - 1) {
            float ddy = fabsf(dS[ty + 2][lx0 + j + 1] - dcen);
            s_sy += ddy * __expf(-sidy[j] * (1.f / 3.f));
        }
    }

    __syncthreads();
    float v;
    v = blockReduceSum(s_gtn, sbuf);   if (tid == 0) atomicAdd(&g_acc[0 * 16], (double)v);
    v = blockReduceSum(s_trust, sbuf); if (tid == 0) atomicAdd(&g_acc[1 * 16], (double)v);
    v = blockReduceSum(s_perr, sbuf);  if (tid == 0) atomicAdd(&g_acc[2 * 16], (double)v);
    v = blockReduceSum(s_valid, sbuf); if (tid == 0) atomicAdd(&g_acc[3 * 16], (double)v);
    v = blockReduceSum(s_sx, sbuf);    if (tid == 0) atomicAdd(&g_acc[7 * 16], (double)v);
    v = blockReduceSum(s_sy, sbuf);    if (tid == 0) atomicAdd(&g_acc[8 * 16], (double)v);
}

// Sign/magnitude from NCC maps + finalize. One thread per half-res cell
// (covers a 2x2 full-res block). Runs after ncc (stream order) and tileA (event join).
__global__ __launch_bounds__(256) void sm_kernel(const float* __restrict__ pred,
                                                 float* __restrict__ out) {
    __shared__ float sbuf[8];
    __shared__ int lastFlag;
    int i = blockIdx.x * 256 + threadIdx.x;     // 0 .. BB*H2*W2-1 exactly
    int x2 = i % W2;
    int y2 = (i / W2) % H2;
    int b = i / (W2 * H2);

    float sS = 0.f, sM = 0.f, sA = 0.f;
    float ncv = g_nc[i];
    if (ncv > 0.3f) {
        float ndv = g_nd[i];
        float sgn = (ndv > 0.f) ? 1.f : ((ndv < 0.f) ? -1.f : 0.f);
        sA = 4.f;
#pragma unroll
        for (int r = 0; r < 2; r++) {
            int row = 2 * y2 + r;
            float2 p = *(const float2*)(pred + (b * HH + row) * WW + 2 * x2);
            sS += fmaxf(-p.x * sgn, 0.f) + fmaxf(-p.y * sgn, 0.f);
            sM += ncv * (fabsf(p.x - ndv) + fabsf(p.y - ndv));
        }
    }
    float v;
    v = blockReduceSum(sS, sbuf); if (threadIdx.x == 0) atomicAdd(&g_acc[4 * 16], (double)v);
    v = blockReduceSum(sM, sbuf); if (threadIdx.x == 0) atomicAdd(&g_acc[5 * 16], (double)v);
    v = blockReduceSum(sA, sbuf); if (threadIdx.x == 0) atomicAdd(&g_acc[6 * 16], (double)v);

    if (threadIdx.x == 0) {
        __threadfence();
        int c = atomicAdd(&g_counter, 1);
        lastFlag = (c == SM_BLOCKS - 1) ? 1 : 0;
    }
    __syncthreads();
    if (lastFlag && threadIdx.x == 0) {
        __threadfence();
        double gtl = g_acc[0 * 16] / fmax(g_acc[1 * 16], 1.0);
        double photo = g_acc[2 * 16] / fmax(g_acc[3 * 16], 1.0);
        double n = fmax(g_acc[6 * 16], 1.0);
        double signmag = 0.3 * (g_acc[4 * 16] / n) + 0.7 * (g_acc[5 * 16] / n);
        double smooth = g_acc[7 * 16] / ((double)BB * HH * (WW - 1)) +
                        g_acc[8 * 16] / ((double)BB * (HH - 1) * WW);
        out[0] = (float)(1.0 * gtl + 1.0 * photo + 0.5 * signmag + 0.1 * smooth);
        g_counter = 0;
    }
}

// ---------------- launch ----------------
extern "C" void kernel_launch(void* const* d_in, const int* in_sizes, int n_in,
                              void* d_out, int out_size) {
    const float* pred  = (const float*)d_in[0];
    const float* gt    = (const float*)d_in[1];
    const float* conf  = (const float*)d_in[2];
    const float* occ   = (const float*)d_in[3];
    const float* left  = (const float*)d_in[4];
    const float* right = (const float*)d_in[5];
    float* out = (float*)d_out;

    // Fork/join: tileA (DRAM-bound) overlaps ncc (crossbar-bound).
    cudaStream_t s2;
    cudaStreamCreateWithFlags(&s2, cudaStreamNonBlocking);
    cudaEvent_t evFork, evJoin;
    cudaEventCreateWithFlags(&evFork, cudaEventDisableTiming);
    cudaEventCreateWithFlags(&evJoin, cudaEventDisableTiming);

    downsample_kernel<<<(BB * H2 * (W2 / 2) + 255) / 256, 256>>>(left, right);
    cudaEventRecord(evFork, 0);
    cudaStreamWaitEvent(s2, evFork, 0);

    dim3 tb(16, 8), tg(WW / 64, HH / 8, BB);
    tileA_kernel<<<tg, tb, 0, s2>>>(pred, gt, conf, occ, left, right);
    ncc_kernel<<<BB * (H2 / 2), 480>>>();

    cudaEventRecord(evJoin, s2);
    cudaStreamWaitEvent(0, evJoin, 0);
    sm_kernel<<<SM_BLOCKS, 256>>>(pred, out);
}

// round 17
// speedup vs baseline: 1.7474x; 1.0188x over previous
#include <cuda_runtime.h>
#include <math.h>

#define BB 4
#define HH 544
#define WW 960
#define H2 272
#define W2 480
#define MD 24
#define SM_BLOCKS 2040   // (BB*HH*WW/4)/256

// ---------------- scratch (no allocations allowed) ----------------
__device__ float g_lg[BB * H2 * W2];
__device__ float g_rg[BB * H2 * W2];
__device__ float g_nd[BB * H2 * W2];
__device__ float g_nc[BB * H2 * W2];
// accumulators padded to one 128B line each to avoid LTS atomic serialization
// idx: 0 gtNum 1 gtDen 2 photoNum 3 photoDen 4 signSum 5 magSum 6 activeSum 7 smx 8 smy
__device__ double g_acc[9 * 16];
__device__ int g_counter;   // zero-initialized; self-resetting

// ---------------- helpers ----------------
__device__ __forceinline__ float blockReduceSum(float v, float* sbuf) {
    int tid = threadIdx.x + threadIdx.y * blockDim.x;
    int lane = tid & 31, wid = tid >> 5;
#pragma unroll
    for (int o = 16; o > 0; o >>= 1) v += __shfl_down_sync(0xffffffffu, v, o);
    if (lane == 0) sbuf[wid] = v;
    __syncthreads();
    int nw = (blockDim.x * blockDim.y + 31) >> 5;
    v = (tid < nw) ? sbuf[tid] : 0.f;
    if (wid == 0) {
#pragma unroll
        for (int o = 16; o > 0; o >>= 1) v += __shfl_down_sync(0xffffffffu, v, o);
    }
    __syncthreads();
    return v;  // valid at tid 0
}

// ---------------- kernels ----------------
// accumulator/counter zeroing (runs before the fork so tileA can start early)
__global__ void zero_kernel() {
    if (threadIdx.x < 9 * 16) g_acc[threadIdx.x] = 0.0;
    if (threadIdx.x == 0) g_counter = 0;
}

// half-res grayscale
__global__ void downsample_kernel(const float* __restrict__ left,
                                  const float* __restrict__ right) {
    int i = blockIdx.x * blockDim.x + threadIdx.x;
    const int NPAIR = W2 / 2;  // 240
    if (i >= BB * H2 * NPAIR) return;
    int px = i % NPAIR;
    int y = (i / NPAIR) % H2;
    int b = i / (NPAIR * H2);
    float l0 = 0.f, l1 = 0.f, r0 = 0.f, r1 = 0.f;
#pragma unroll
    for (int c = 0; c < 3; c++) {
        int base = ((b * 3 + c) * HH + 2 * y) * WW + 4 * px;
        float4 a0 = *(const float4*)(left + base);
        float4 a1 = *(const float4*)(left + base + WW);
        l0 += (a0.x + a0.y + a1.x + a1.y);
        l1 += (a0.z + a0.w + a1.z + a1.w);
        float4 b0 = *(const float4*)(right + base);
        float4 b1 = *(const float4*)(right + base + WW);
        r0 += (b0.x + b0.y + b1.x + b1.y);
        r1 += (b0.z + b0.w + b1.z + b1.w);
    }
    const float S = 0.25f / 3.0f;
    int o = (b * H2 + y) * W2 + 2 * px;
    *(float2*)(g_lg + o) = make_float2(l0 * S, l1 * S);
    *(float2*)(g_rg + o) = make_float2(r0 * S, r1 * S);
}

// NCC disparity search: EXACT round-9 version (proven local optimum).
// One CTA per (b, PAIR of half-res rows), 480 threads. Row y0+1 stats by
// register rolling; division-free argmax.
__global__ void __launch_bounds__(480, 2) ncc_kernel() {
    __shared__ float rgS[12][528];                        // rows y0-5..y0+6, zero-padded +/-24
    __shared__ float crp0[560], cr2p0[560];               // rg column sums row0 window (idx=x+40)
    __shared__ float crp1[560], cr2p1[560];               // rg column sums row1 window
    __shared__ float Hcr0[528], Hcr20[528];               // 11-box of crp0 at u=idx-24
    __shared__ float Hcr1[528], Hcr21[528];               // 11-box of crp1
    __shared__ float ccS[2][6][496];                      // cross column sums, idx = x+8
    float* clp0 = &ccS[0][0][0];                          // setup-only aliases (560 each)
    float* cl2p0 = clp0 + 560;
    float* clp1 = clp0 + 1120;
    float* cl2p1 = clp0 + 1680;
    const float NORM = 1.0f / 121.0f;

    int pr = blockIdx.x;
    int b = pr / (H2 / 2);
    int yp = pr - b * (H2 / 2);
    int y0 = 2 * yp;
    int x = threadIdx.x;
    const float* lgB = g_lg + b * H2 * W2;
    const float* rgB = g_rg + b * H2 * W2;

    float lgR[12];
    float cr0 = 0.f, cr20 = 0.f, cl0 = 0.f, cl20 = 0.f;
    float rv0 = 0.f, rv11 = 0.f;
#pragma unroll
    for (int r = 0; r < 12; r++) {
        int yy = y0 + r - 5;
        float lv = 0.f, rv = 0.f;
        if (yy >= 0 && yy < H2) { lv = lgB[yy * W2 + x]; rv = rgB[yy * W2 + x]; }
        lgR[r] = lv;
        rgS[r][x + 24] = rv;
        if (x < 24) { rgS[r][x] = 0.f; rgS[r][x + 504] = 0.f; }
        if (r < 11) { cr0 += rv; cr20 += rv * rv; cl0 += lv; cl20 += lv * lv; }
        if (r == 0) rv0 = rv;
        if (r == 11) rv11 = rv;
    }
    float cr1 = cr0 - rv0 + rv11;
    float cr21 = cr20 - rv0 * rv0 + rv11 * rv11;
    float cl1 = cl0 - lgR[0] + lgR[11];
    float cl21 = cl20 - lgR[0] * lgR[0] + lgR[11] * lgR[11];

    crp0[x + 40] = cr0; cr2p0[x + 40] = cr20;
    crp1[x + 40] = cr1; cr2p1[x + 40] = cr21;
    clp0[x + 40] = cl0; cl2p0[x + 40] = cl20;
    clp1[x + 40] = cl1; cl2p1[x + 40] = cl21;
    if (x < 40) {
        crp0[x] = 0.f; cr2p0[x] = 0.f; crp1[x] = 0.f; cr2p1[x] = 0.f;
        clp0[x] = 0.f; cl2p0[x] = 0.f; clp1[x] = 0.f; cl2p1[x] = 0.f;
    }
    if (x >= 440) {
        crp0[x + 80] = 0.f; cr2p0[x + 80] = 0.f; crp1[x + 80] = 0.f; cr2p1[x + 80] = 0.f;
        clp0[x + 80] = 0.f; cl2p0[x + 80] = 0.f; clp1[x + 80] = 0.f; cl2p1[x + 80] = 0.f;
    }
    __syncthreads();

    // Hcr[i] = 11-box of cr centered at col i-24 : taps crp[i+11..i+21]
    for (int i = x; i < 528; i += 480) {
        float s0 = 0.f, s20 = 0.f, s1 = 0.f, s21 = 0.f;
#pragma unroll
        for (int k = 0; k < 11; k++) {
            s0 += crp0[i + 11 + k]; s20 += cr2p0[i + 11 + k];
            s1 += crp1[i + 11 + k]; s21 += cr2p1[i + 11 + k];
        }
        Hcr0[i] = s0; Hcr20[i] = s20; Hcr1[i] = s1; Hcr21[i] = s21;
    }
    // left stats for both rows
    float lm0 = 0.f, lq0 = 0.f, lm1 = 0.f, lq1 = 0.f;
#pragma unroll
    for (int k = 0; k < 11; k++) {
        lm0 += clp0[x + 35 + k]; lq0 += cl2p0[x + 35 + k];
        lm1 += clp1[x + 35 + k]; lq1 += cl2p1[x + 35 + k];
    }
    lm0 *= NORM; lq0 *= NORM; lm1 *= NORM; lq1 *= NORM;
    float ls0 = sqrtf(fmaxf(lq0 - lm0 * lm0, 1e-8f));
    float ls1 = sqrtf(fmaxf(lq1 - lm1 * lm1, 1e-8f));
    __syncthreads();   // clp reads done; ccS region now free

    // zero ccS pads (idx 0..7, 488..495)
    if (x < 8) {
#pragma unroll
        for (int rr = 0; rr < 2; rr++)
#pragma unroll
            for (int j = 0; j < 6; j++) { ccS[rr][j][x] = 0.f; ccS[rr][j][488 + x] = 0.f; }
    }

    // division-free argmax state: best = bestNum/bestDen, bestDen > 0 always
    float bestN0 = -1.f, bestDen0 = 1.f, bestD0 = 0.f;
    float bestN1 = -1.f, bestDen1 = 1.f, bestD1 = 0.f;
    bool interior = (x >= 5 && x < 475);
    for (int g = 0; g < 8; g++) {
        float cc0r[6], cc1r[6];
#pragma unroll
        for (int j = 0; j < 6; j++) {
            int idx = g * 6 + j;
            int d = (idx < 24) ? (idx - 24) : (idx - 23);
            int u = x + d + 24;
            float w0v = rgS[0][u];
            float s = lgR[0] * w0v;
#pragma unroll
            for (int r = 1; r < 11; r++) s += lgR[r] * rgS[r][u];
            cc0r[j] = s;
            float w11v = rgS[11][u];
            cc1r[j] = s - lgR[0] * w0v + lgR[11] * w11v;
            ccS[0][j][x + 8] = s;
            ccS[1][j][x + 8] = cc1r[j];
        }
        __syncthreads();
#pragma unroll
        for (int j = 0; j < 6; j++) {
            int idx = g * 6 + j;
            int d = (idx < 24) ? (idx - 24) : (idx - 23);
            // cross boxes: own column kept in register (10 taps each)
            float cross0 = cc0r[j], cross1 = cc1r[j];
#pragma unroll
            for (int k = -5; k < 0; k++) { cross0 += ccS[0][j][x + 8 + k]; cross1 += ccS[1][j][x + 8 + k]; }
#pragma unroll
            for (int k = 1; k <= 5; k++) { cross0 += ccS[0][j][x + 8 + k]; cross1 += ccS[1][j][x + 8 + k]; }
            float rm0_, r20_, rm1_, r21_;
            if (interior) {
                int u = x + d + 24;
                rm0_ = Hcr0[u]; r20_ = Hcr20[u]; rm1_ = Hcr1[u]; r21_ = Hcr21[u];
            } else {
                rm0_ = 0.f; r20_ = 0.f; rm1_ = 0.f; r21_ = 0.f;
#pragma unroll
                for (int k = -5; k <= 5; k++) {
                    int uu = x + k;
                    if (uu >= 0 && uu < W2) {
                        rm0_ += crp0[uu + d + 40]; r20_ += cr2p0[uu + d + 40];
                        rm1_ += crp1[uu + d + 40]; r21_ += cr2p1[uu + d + 40];
                    }
                }
            }
            float rm = rm0_ * NORM;
            float rstd = sqrtf(fmaxf(r20_ * NORM - rm * rm, 1e-8f));
            float num = cross0 * NORM - lm0 * rm;
            float den = ls0 * rstd + 1e-8f;
            if (num * bestDen0 > bestN0 * den) { bestN0 = num; bestDen0 = den; bestD0 = (float)d; }
            rm = rm1_ * NORM;
            rstd = sqrtf(fmaxf(r21_ * NORM - rm * rm, 1e-8f));
            num = cross1 * NORM - lm1 * rm;
            den = ls1 * rstd + 1e-8f;
            if (num * bestDen1 > bestN1 * den) { bestN1 = num; bestDen1 = den; bestD1 = (float)d; }
        }
        __syncthreads();
    }
    int o = (b * H2 + y0) * W2 + x;
    g_nd[o] = bestD0 * 2.0f;
    g_nc[o] = fmaxf(bestN0 / bestDen0, 0.f);
    g_nd[o + W2] = bestD1 * 2.0f;
    g_nc[o + W2] = fmaxf(bestN1 / bestDen1, 0.f);
}

// Photometric + GT anchor + smoothness ONLY (independent of ncc AND downsample
// -> runs concurrently with both on a forked stream). 64x8 tiles, 128 threads,
// 4 outputs/thread.
__global__ __launch_bounds__(128) void tileA_kernel(const float* __restrict__ pred,
                                                    const float* __restrict__ gt,
                                                    const float* __restrict__ conf,
                                                    const float* __restrict__ occ,
                                                    const float* __restrict__ left,
                                                    const float* __restrict__ right) {
    __shared__ float lS[3][10][66];
    __shared__ float wS[3][10][66];
    __shared__ float dS[10][66];
    __shared__ float sbuf[8];
    int b = blockIdx.z;
    int tx0 = blockIdx.x * 64, ty0 = blockIdx.y * 8;
    int tid = threadIdx.y * 16 + threadIdx.x;

    // halo load: compute warped right on the fly
    for (int i = tid; i < 10 * 66; i += 128) {
        int col = i % 66;
        int rrow = i / 66;
        int gx = tx0 + col - 1, gy = ty0 + rrow - 1;
        if (gx >= 0 && gx < WW && gy >= 0 && gy < HH) {
            float disp = pred[(b * HH + gy) * WW + gx];
            dS[rrow][col] = disp;
            float xs = (float)gx - disp;
            float xc = fminf(fmaxf(xs, 0.f), (float)(WW - 1));
            float x0f = floorf(xc);
            float w = xc - x0f;
            int x0i = (int)x0f;
            int x1i = min(x0i + 1, WW - 1);
#pragma unroll
            for (int c = 0; c < 3; c++) {
                const float* R = right + ((b * 3 + c) * HH + gy) * WW;
                wS[c][rrow][col] = R[x0i] * (1.f - w) + R[x1i] * w;
                lS[c][rrow][col] = left[((b * 3 + c) * HH + gy) * WW + gx];
            }
        } else {
            dS[rrow][col] = 0.f;
#pragma unroll
            for (int c = 0; c < 3; c++) { wS[c][rrow][col] = 0.f; lS[c][rrow][col] = 0.f; }
        }
    }
    __syncthreads();

    int tx = threadIdx.x, ty = threadIdx.y;
    int lx0 = 4 * tx;                 // local col of first output
    int gx0 = tx0 + lx0, gy = ty0 + ty;

    float ssAcc[4] = {0, 0, 0, 0}, l1Acc[4] = {0, 0, 0, 0};
    float sidx[4] = {0, 0, 0, 0}, sidy[4] = {0, 0, 0, 0};
    const float N9 = 1.f / 9.f;
    const float C1 = 1e-4f, C2 = 9e-4f;
#pragma unroll
    for (int c = 0; c < 3; c++) {
        float win[4][5];
#pragma unroll
        for (int j = 0; j < 4; j++)
#pragma unroll
            for (int q = 0; q < 5; q++) win[j][q] = 0.f;
        float prev1 = 0.f;
#pragma unroll
        for (int u = 0; u < 6; u++) {
            float l0 = lS[c][ty][lx0 + u], l1 = lS[c][ty + 1][lx0 + u], l2 = lS[c][ty + 2][lx0 + u];
            float m0 = wS[c][ty][lx0 + u], m1 = wS[c][ty + 1][lx0 + u], m2 = wS[c][ty + 2][lx0 + u];
            float cA = l0 + l1 + l2;
            float cB = m0 + m1 + m2;
            float cC = l0 * l0 + l1 * l1 + l2 * l2;
            float cD = m0 * m0 + m1 * m1 + m2 * m2;
            float cE = l0 * m0 + l1 * m1 + l2 * m2;
#pragma unroll
            for (int j = 0; j < 4; j++) {
                if (u >= j && u <= j + 2) {
                    win[j][0] += cA; win[j][1] += cB; win[j][2] += cC;
                    win[j][3] += cD; win[j][4] += cE;
                }
            }
            if (u >= 1 && u <= 4) {
                l1Acc[u - 1] += fabsf(l1 - m1);
                sidy[u - 1] += fabsf(l2 - l1);
            }
            if (u >= 2) sidx[u - 2] += fabsf(l1 - prev1);
            prev1 = l1;
        }
#pragma unroll
        for (int j = 0; j < 4; j++) {
            float mx = win[j][0] * N9, my = win[j][1] * N9;
            float vx = fmaxf(win[j][2] * N9 - mx * mx, 0.f);
            float vy = fmaxf(win[j][3] * N9 - my * my, 0.f);
            float cxy = win[j][4] * N9 - mx * my;
            float nn = (2.f * mx * my + C1) * (2.f * cxy + C2);
            float dd = (mx * mx + my * my + C1) * (vx + vy + C2);
            ssAcc[j] += fminf(fmaxf((1.f - nn / dd) * 0.5f, 0.f), 1.f);
        }
    }

    int gi0 = (b * HH + gy) * WW + gx0;
    float4 gtv = *(const float4*)(gt + gi0);
    float4 cfv = *(const float4*)(conf + gi0);
    float4 ocv = *(const float4*)(occ + gi0);
    float gtA[4] = {gtv.x, gtv.y, gtv.z, gtv.w};
    float cfA[4] = {cfv.x, cfv.y, cfv.z, cfv.w};
    float ocA[4] = {ocv.x, ocv.y, ocv.z, ocv.w};

    float s_gtn = 0.f, s_trust = 0.f, s_perr = 0.f, s_valid = 0.f;
    float s_sx = 0.f, s_sy = 0.f;
#pragma unroll
    for (int j = 0; j < 4; j++) {
        int gx = gx0 + j;
        float dcen = dS[ty + 1][lx0 + j + 1];
        float xs = (float)gx - dcen;
        float valid = (xs > 0.f && xs < (float)(WW - 1)) ? 1.f : 0.f;
        float perr = (0.85f * (ssAcc[j] * (1.f / 3.f)) + 0.15f * (l1Acc[j] * (1.f / 3.f))) * valid;
        s_perr += perr; s_valid += valid;

        float g = gtA[j];
        float trust = (g > 2.f) ? cfA[j] * ocA[j] : 0.f;
        s_gtn += trust * fabsf(dcen - g);
        s_trust += trust;

        if (gx < WW - 1) {
            float ddx = fabsf(dS[ty + 1][lx0 + j + 2] - dcen);
            s_sx += ddx * __expf(-sidx[j] * (1.f / 3.f));
        }
        if (gy < HH - 1) {
            float ddy = fabsf(dS[ty + 2][lx0 + j + 1] - dcen);
            s_sy += ddy * __expf(-sidy[j] * (1.f / 3.f));
        }
    }

    __syncthreads();
    float v;
    v = blockReduceSum(s_gtn, sbuf);   if (tid == 0) atomicAdd(&g_acc[0 * 16], (double)v);
    v = blockReduceSum(s_trust, sbuf); if (tid == 0) atomicAdd(&g_acc[1 * 16], (double)v);
    v = blockReduceSum(s_perr, sbuf);  if (tid == 0) atomicAdd(&g_acc[2 * 16], (double)v);
    v = blockReduceSum(s_valid, sbuf); if (tid == 0) atomicAdd(&g_acc[3 * 16], (double)v);
    v = blockReduceSum(s_sx, sbuf);    if (tid == 0) atomicAdd(&g_acc[7 * 16], (double)v);
    v = blockReduceSum(s_sy, sbuf);    if (tid == 0) atomicAdd(&g_acc[8 * 16], (double)v);
}

// Sign/magnitude + finalize. Coalesced full-res streaming: one thread per 4
// consecutive full-res pixels (float4 pred, aligned float2 nc/nd).
__global__ __launch_bounds__(256) void sm_kernel(const float* __restrict__ pred,
                                                 float* __restrict__ out) {
    __shared__ float sbuf[8];
    __shared__ int lastFlag;
    int i = blockIdx.x * 256 + threadIdx.x;     // quad index, 0 .. BB*HH*WW/4-1
    int q = i * 4;
    int gx = q % WW;                             // multiple of 4
    int gy = (q / WW) % HH;
    int b = q / (WW * HH);

    float4 p = *(const float4*)(pred + q);
    int hbase = (b * H2 + (gy >> 1)) * W2 + (gx >> 1);   // even -> float2 aligned
    float2 nc = *(const float2*)(g_nc + hbase);
    float2 nd = *(const float2*)(g_nd + hbase);

    float sS = 0.f, sM = 0.f, sA = 0.f;
    {
        bool act = nc.x > 0.3f;
        float m = act ? 1.f : 0.f;
        float sgn = (nd.x > 0.f) ? 1.f : ((nd.x < 0.f) ? -1.f : 0.f);
        sA += 2.f * m;
        sS += m * (fmaxf(-p.x * sgn, 0.f) + fmaxf(-p.y * sgn, 0.f));
        sM += m * nc.x * (fabsf(p.x - nd.x) + fabsf(p.y - nd.x));
    }
    {
        bool act = nc.y > 0.3f;
        float m = act ? 1.f : 0.f;
        float sgn = (nd.y > 0.f) ? 1.f : ((nd.y < 0.f) ? -1.f : 0.f);
        sA += 2.f * m;
        sS += m * (fmaxf(-p.z * sgn, 0.f) + fmaxf(-p.w * sgn, 0.f));
        sM += m * nc.y * (fabsf(p.z - nd.y) + fabsf(p.w - nd.y));
    }
    float v;
    v = blockReduceSum(sS, sbuf); if (threadIdx.x == 0) atomicAdd(&g_acc[4 * 16], (double)v);
    v = blockReduceSum(sM, sbuf); if (threadIdx.x == 0) atomicAdd(&g_acc[5 * 16], (double)v);
    v = blockReduceSum(sA, sbuf); if (threadIdx.x == 0) atomicAdd(&g_acc[6 * 16], (double)v);

    if (threadIdx.x == 0) {
        __threadfence();
        int c = atomicAdd(&g_counter, 1);
        lastFlag = (c == SM_BLOCKS - 1) ? 1 : 0;
    }
    __syncthreads();
    if (lastFlag && threadIdx.x == 0) {
        __threadfence();
        double gtl = g_acc[0 * 16] / fmax(g_acc[1 * 16], 1.0);
        double photo = g_acc[2 * 16] / fmax(g_acc[3 * 16], 1.0);
        double n = fmax(g_acc[6 * 16], 1.0);
        double signmag = 0.3 * (g_acc[4 * 16] / n) + 0.7 * (g_acc[5 * 16] / n);
        double smooth = g_acc[7 * 16] / ((double)BB * HH * (WW - 1)) +
                        g_acc[8 * 16] / ((double)BB * (HH - 1) * WW);
        out[0] = (float)(1.0 * gtl + 1.0 * photo + 0.5 * signmag + 0.1 * smooth);
        g_counter = 0;
    }
}

// ---------------- launch ----------------
extern "C" void kernel_launch(void* const* d_in, const int* in_sizes, int n_in,
                              void* d_out, int out_size) {
    const float* pred  = (const float*)d_in[0];
    const float* gt    = (const float*)d_in[1];
    const float* conf  = (const float*)d_in[2];
    const float* occ   = (const float*)d_in[3];
    const float* left  = (const float*)d_in[4];
    const float* right = (const float*)d_in[5];
    float* out = (float*)d_out;

    // Fork/join: tileA (DRAM-bound) overlaps downsample + ncc (crossbar-bound).
    cudaStream_t s2;
    cudaStreamCreateWithFlags(&s2, cudaStreamNonBlocking);
    cudaEvent_t evFork, evJoin;
    cudaEventCreateWithFlags(&evFork, cudaEventDisableTiming);
    cudaEventCreateWithFlags(&evJoin, cudaEventDisableTiming);

    zero_kernel<<<1, 160>>>();
    cudaEventRecord(evFork, 0);
    cudaStreamWaitEvent(s2, evFork, 0);

    dim3 tb(16, 8), tg(WW / 64, HH / 8, BB);
    tileA_kernel<<<tg, tb, 0, s2>>>(pred, gt, conf, occ, left, right);
    downsample_kernel<<<(BB * H2 * (W2 / 2) + 255) / 256, 256>>>(left, right);
    ncc_kernel<<<BB * (H2 / 2), 480>>>();

    cudaEventRecord(evJoin, s2);
    cudaStreamWaitEvent(0, evJoin, 0);
    sm_kernel<<<SM_BLOCKS, 256>>>(pred, out);
}